// round 5
// baseline (speedup 1.0000x reference)
#include <cuda_runtime.h>
#include <math.h>

#define B_SAMPLES 128
#define T_LEN     8192
#define C_CLASSES 64
#define OUT_LEN   8

#define K1_THREADS 256
#define POS_PER_CTA (K1_THREADS / 4)            // 4 threads per position
#define K2_THREADS 1024
#define EPT 8                                    // contiguous elems per thread

// Scratch (allocation-free __device__ globals)
__device__ __align__(16) float         g_conf[B_SAMPLES * T_LEN];
__device__ __align__(16) unsigned char g_pred[B_SAMPLES * T_LEN];

// Order-preserving float -> u32 key (total order). Higher float => higher key.
__device__ __forceinline__ unsigned f2key(float f) {
    unsigned b = __float_as_uint(f);
    return (b & 0x80000000u) ? ~b : (b | 0x80000000u);
}
// voted values are finite positive or -inf; finite => key has top bit set.
#define KEY_VALID(k) ((k) & 0x80000000u)

// ---------------------------------------------------------------------------
// K1: softmax confidence (max prob) + argmax, 4 threads per position.
// x read with streaming hint (__ldcs) so conf/pred stay L2-resident for K2.
// ---------------------------------------------------------------------------
__global__ __launch_bounds__(K1_THREADS)
void softmax_conf_kernel(const float* __restrict__ x) {
    const int tid  = threadIdx.x;
    const int part = tid & 3;            // which 16-class chunk
    const size_t pos = (size_t)blockIdx.x * POS_PER_CTA + (tid >> 2);

    const float4* __restrict__ p =
        (const float4*)(x + pos * C_CLASSES + part * 16);
    float4 v0 = __ldcs(p + 0);
    float4 v1 = __ldcs(p + 1);
    float4 v2 = __ldcs(p + 2);
    float4 v3 = __ldcs(p + 3);

    float r[16] = {v0.x, v0.y, v0.z, v0.w, v1.x, v1.y, v1.z, v1.w,
                   v2.x, v2.y, v2.z, v2.w, v3.x, v3.y, v3.z, v3.w};

    float m = r[0];
    int   am = 0;
    #pragma unroll
    for (int c = 1; c < 16; c++)
        if (r[c] > m) { m = r[c]; am = c; }
    int amg = part * 16 + am;

    #pragma unroll
    for (int d = 1; d < 4; d <<= 1) {
        float om = __shfl_xor_sync(0xFFFFFFFFu, m,   d);
        int   oa = __shfl_xor_sync(0xFFFFFFFFu, amg, d);
        if (om > m || (om == m && oa < amg)) { m = om; amg = oa; }
    }

    float s = 0.0f;
    #pragma unroll
    for (int c = 0; c < 16; c++)
        s += expf(r[c] - m);
    #pragma unroll
    for (int d = 1; d < 4; d <<= 1)
        s += __shfl_xor_sync(0xFFFFFFFFu, s, d);

    if (part == 0) {
        g_conf[pos] = 1.0f / s;
        g_pred[pos] = (unsigned char)amg;
    }
}

// ---------------------------------------------------------------------------
// K2: per-sample RLE + top-8. One CTA (1024 thr) per sample.
// voted confidences live as order-preserving u32 keys; each selection round is
// redux.max (value) + redux.min (index, ties -> lowest = lax.top_k semantics).
// ---------------------------------------------------------------------------
__global__ __launch_bounds__(K2_THREADS)
void topk_kernel(float* __restrict__ out) {
    __shared__ unsigned char spred[T_LEN];           // 8 KB
    __shared__ unsigned candk[OUT_LEN * 32];         // [round][warp]
    __shared__ int      candi[OUT_LEN * 32];
    __shared__ unsigned outk[OUT_LEN];
    __shared__ int      outi[OUT_LEN];

    const int b    = blockIdx.x;
    const int tid  = threadIdx.x;
    const int lane = tid & 31;
    const int wid  = tid >> 5;
    const size_t off = (size_t)b * T_LEN;
    const int t0 = tid * EPT;

    // ---- Front-batched, unconditional global loads (L2-resident) ----
    uint2  pv2 = ((const uint2*)(g_pred + off))[tid];
    float4 c0  = ((const float4*)(g_conf + off))[tid * 2];
    float4 c1  = ((const float4*)(g_conf + off))[tid * 2 + 1];

    ((uint2*)spred)[tid] = pv2;
    __syncthreads();

    unsigned char pb[EPT];
    pb[0] = (unsigned char)(pv2.x);        pb[1] = (unsigned char)(pv2.x >> 8);
    pb[2] = (unsigned char)(pv2.x >> 16);  pb[3] = (unsigned char)(pv2.x >> 24);
    pb[4] = (unsigned char)(pv2.y);        pb[5] = (unsigned char)(pv2.y >> 8);
    pb[6] = (unsigned char)(pv2.y >> 16);  pb[7] = (unsigned char)(pv2.y >> 24);
    float cf[EPT] = {c0.x, c0.y, c0.z, c0.w, c1.x, c1.y, c1.z, c1.w};

    unsigned char prev = (tid == 0) ? (unsigned char)(pb[0] ^ 1) : spred[t0 - 1];

    // voted keys (0 = invalid/consumed; finite voted => top bit set)
    unsigned lk[EPT];
    #pragma unroll
    for (int j = 0; j < EPT; j++) {
        unsigned char cur = pb[j];
        unsigned char before = (j == 0) ? prev : pb[j - 1];
        bool start = (t0 + j == 0) || (cur != before);
        unsigned kk = 0;
        if (start) {
            int cnt = 1;
            int jj = j + 1;
            while (jj < EPT && pb[jj] == cur) { cnt++; jj++; }   // reg scan
            if (jj == EPT) {                                      // rare spill
                int e = t0 + EPT;
                while (e < T_LEN && spred[e] == cur) { cnt++; e++; }
            }
            kk = f2key(cf[j] * (float)cnt);
        }
        lk[j] = kk;
    }

    // ---- Phase A: per-warp top-8 via redux (no barriers) ----
    // Cached per-thread best; only the invalidated owner rescans.
    unsigned bk = lk[0];
    int      bj = 0;
    #pragma unroll
    for (int j = 1; j < EPT; j++)
        if (lk[j] > bk) { bk = lk[j]; bj = j; }      // j asc => first-max tie

    #pragma unroll
    for (int k = 0; k < OUT_LEN; k++) {
        unsigned wk = __reduce_max_sync(0xFFFFFFFFu, bk);
        int ci = (bk == wk) ? (t0 + bj) : 0x7FFFFFFF;
        int wi = (int)__reduce_min_sync(0xFFFFFFFFu, (unsigned)ci);
        if (lane == 0) {
            candk[k * 32 + wid] = wk;
            candi[k * 32 + wid] = wi;
        }
        if ((wi >> 3) == tid) {                      // owner: consume + rescan
            lk[wi & (EPT - 1)] = 0;
            bk = lk[0]; bj = 0;
            #pragma unroll
            for (int j = 1; j < EPT; j++)
                if (lk[j] > bk) { bk = lk[j]; bj = j; }
        }
    }
    __syncthreads();

    // ---- Phase B: warp 0 merges 32x8 candidates ----
    if (wid == 0) {
        unsigned ck[OUT_LEN];
        int      ci8[OUT_LEN];
        #pragma unroll
        for (int r = 0; r < OUT_LEN; r++) {
            ck[r]  = candk[r * 32 + lane];
            ci8[r] = candi[r * 32 + lane];
        }
        // Per-lane candidates are key-desc / index-asc on ties: strict >
        // local scan keeps lowest index within a lane.
        unsigned bk2 = ck[0];
        int bi2 = ci8[0], br2 = 0;
        #pragma unroll
        for (int r = 1; r < OUT_LEN; r++)
            if (ck[r] > bk2) { bk2 = ck[r]; bi2 = ci8[r]; br2 = r; }

        #pragma unroll
        for (int k = 0; k < OUT_LEN; k++) {
            unsigned wk = __reduce_max_sync(0xFFFFFFFFu, bk2);
            int ci = (bk2 == wk) ? bi2 : 0x7FFFFFFF;
            int wi = (int)__reduce_min_sync(0xFFFFFFFFu, (unsigned)ci);
            if (lane == 0) { outk[k] = wk; outi[k] = wi; }
            if (bk2 == wk && bi2 == wi) {            // unique index -> 1 owner
                ck[br2] = 0;
                bk2 = ck[0]; bi2 = ci8[0]; br2 = 0;
                #pragma unroll
                for (int r = 1; r < OUT_LEN; r++)
                    if (ck[r] > bk2) { bk2 = ck[r]; bi2 = ci8[r]; br2 = r; }
            }
        }
    }
    __syncthreads();

    if (tid < OUT_LEN) {
        unsigned k = outk[tid];
        float o = 0.0f;                               // pad-with-zero path
        if (KEY_VALID(k)) o = (float)spred[outi[tid]];
        out[(size_t)b * OUT_LEN + tid] = o;
    }
}

// ---------------------------------------------------------------------------
extern "C" void kernel_launch(void* const* d_in, const int* in_sizes, int n_in,
                              void* d_out, int out_size) {
    const float* x = (const float*)d_in[0];
    float* out = (float*)d_out;

    const int n_pos = B_SAMPLES * T_LEN;
    softmax_conf_kernel<<<n_pos / POS_PER_CTA, K1_THREADS>>>(x);
    topk_kernel<<<B_SAMPLES, K2_THREADS>>>(out);
}

// round 6
// speedup vs baseline: 1.3596x; 1.3596x over previous
#include <cuda_runtime.h>
#include <math.h>

#define B_SAMPLES 128
#define T_LEN     8192
#define C_CLASSES 64
#define OUT_LEN   8

#define THREADS   1024
#define POS_PER_PASS (THREADS / 4)        // 4 threads per position -> 256
#define N_PASSES  (T_LEN / POS_PER_PASS)  // 32
#define EPT       (T_LEN / THREADS)       // 8 contiguous elems per thread

// ---------------------------------------------------------------------------
// Fused kernel: one CTA per sample.
// Phase 1 (stream): softmax confidence + argmax, 4 threads/position,
//   coalesced float4 loads (warp = 2KB contiguous), results -> smem.
// Phase 2 (tail): RLE + top-8 by voted confidence, all smem/registers.
// ---------------------------------------------------------------------------
__global__ __launch_bounds__(THREADS, 1)
void fused_kernel(const float* __restrict__ x, float* __restrict__ out) {
    __shared__ float         sconf[T_LEN];          // 32 KB
    __shared__ unsigned char spred[T_LEN];          //  8 KB
    __shared__ float candv[OUT_LEN * 32];           // [round][warp]
    __shared__ int   candi[OUT_LEN * 32];
    __shared__ float outv[OUT_LEN];
    __shared__ int   outi[OUT_LEN];

    const int b    = blockIdx.x;
    const int tid  = threadIdx.x;
    const int lane = tid & 31;
    const int wid  = tid >> 5;
    const int part = tid & 3;                       // 16-class chunk
    const int posL = tid >> 2;                      // position within pass

    const float* __restrict__ xb = x + (size_t)b * T_LEN * C_CLASSES;

    // ================= Phase 1: stream 2MB, compute conf/pred =================
    for (int pass = 0; pass < N_PASSES; pass++) {
        const int pos = pass * POS_PER_PASS + posL;
        const float4* __restrict__ p =
            (const float4*)(xb + (size_t)pos * C_CLASSES + part * 16);
        float4 v0 = p[0], v1 = p[1], v2 = p[2], v3 = p[3];

        float r[16] = {v0.x, v0.y, v0.z, v0.w, v1.x, v1.y, v1.z, v1.w,
                       v2.x, v2.y, v2.z, v2.w, v3.x, v3.y, v3.z, v3.w};

        // Local max + first-occurrence argmax over this 16-chunk
        float m = r[0];
        int   am = 0;
        #pragma unroll
        for (int c = 1; c < 16; c++)
            if (r[c] > m) { m = r[c]; am = c; }
        int amg = part * 16 + am;

        // Combine across the 4 cooperating lanes (xor 1,2 stays in group)
        #pragma unroll
        for (int d = 1; d < 4; d <<= 1) {
            float om = __shfl_xor_sync(0xFFFFFFFFu, m,   d);
            int   oa = __shfl_xor_sync(0xFFFFFFFFu, amg, d);
            if (om > m || (om == m && oa < amg)) { m = om; amg = oa; }
        }

        float s = 0.0f;
        #pragma unroll
        for (int c = 0; c < 16; c++)
            s += expf(r[c] - m);
        #pragma unroll
        for (int d = 1; d < 4; d <<= 1)
            s += __shfl_xor_sync(0xFFFFFFFFu, s, d);

        if (part == 0) {
            sconf[pos] = 1.0f / s;
            spred[pos] = (unsigned char)amg;
        }
    }
    __syncthreads();

    // ================= Phase 2: RLE + top-8 (smem/registers) =================
    const int t0 = tid * EPT;

    uint2 pv2 = ((const uint2*)spred)[tid];
    unsigned char pb[EPT];
    pb[0] = (unsigned char)(pv2.x);        pb[1] = (unsigned char)(pv2.x >> 8);
    pb[2] = (unsigned char)(pv2.x >> 16);  pb[3] = (unsigned char)(pv2.x >> 24);
    pb[4] = (unsigned char)(pv2.y);        pb[5] = (unsigned char)(pv2.y >> 8);
    pb[6] = (unsigned char)(pv2.y >> 16);  pb[7] = (unsigned char)(pv2.y >> 24);

    float4 c0 = ((const float4*)sconf)[tid * 2];
    float4 c1 = ((const float4*)sconf)[tid * 2 + 1];
    float cf[EPT] = {c0.x, c0.y, c0.z, c0.w, c1.x, c1.y, c1.z, c1.w};

    unsigned char prev = (tid == 0) ? (unsigned char)(pb[0] ^ 1) : spred[t0 - 1];

    float lv[EPT];
    #pragma unroll
    for (int j = 0; j < EPT; j++) {
        unsigned char cur = pb[j];
        unsigned char before = (j == 0) ? prev : pb[j - 1];
        bool start = (t0 + j == 0) || (cur != before);
        float v = -INFINITY;
        if (start) {
            int cnt = 1;
            int jj = j + 1;
            while (jj < EPT && pb[jj] == cur) { cnt++; jj++; }   // reg scan
            if (jj == EPT) {                                      // rare spill
                int e = t0 + EPT;
                while (e < T_LEN && spred[e] == cur) { cnt++; e++; }
            }
            v = cf[j] * (float)cnt;
        }
        lv[j] = v;
    }

    // ---- Phase A: per-warp top-8 (no barriers) ----
    #pragma unroll
    for (int k = 0; k < OUT_LEN; k++) {
        float bv = lv[0];
        int   bj = 0;
        #pragma unroll
        for (int j = 1; j < EPT; j++)
            if (lv[j] > bv) { bv = lv[j]; bj = j; }   // j asc = index asc
        int bi = t0 + bj;

        #pragma unroll
        for (int d = 16; d > 0; d >>= 1) {
            float ov = __shfl_xor_sync(0xFFFFFFFFu, bv, d);
            int   oi = __shfl_xor_sync(0xFFFFFFFFu, bi, d);
            if (ov > bv || (ov == bv && oi < bi)) { bv = ov; bi = oi; }
        }
        if (lane == 0) {
            candv[k * 32 + wid] = bv;
            candi[k * 32 + wid] = bi;
        }
        if ((bi >> 3) == tid)              // owner invalidates
            lv[bi & (EPT - 1)] = -INFINITY;
    }
    __syncthreads();

    // ---- Phase B: warp 0 merges 32x8 candidates ----
    if (wid == 0) {
        float cv[OUT_LEN];
        int   ci[OUT_LEN];
        #pragma unroll
        for (int r = 0; r < OUT_LEN; r++) {
            cv[r] = candv[r * 32 + lane];
            ci[r] = candi[r * 32 + lane];
        }
        #pragma unroll
        for (int k = 0; k < OUT_LEN; k++) {
            // Per-lane candidates are value-desc / index-asc on ties, so a
            // strict > scan keeps the lowest-index tie, matching lax.top_k.
            float bv = cv[0];
            int   bi = ci[0], br = 0;
            #pragma unroll
            for (int r = 1; r < OUT_LEN; r++)
                if (cv[r] > bv) { bv = cv[r]; bi = ci[r]; br = r; }
            float mv = bv; int mi = bi;
            #pragma unroll
            for (int d = 16; d > 0; d >>= 1) {
                float ov = __shfl_xor_sync(0xFFFFFFFFu, mv, d);
                int   oi = __shfl_xor_sync(0xFFFFFFFFu, mi, d);
                if (ov > mv || (ov == mv && oi < mi)) { mv = ov; mi = oi; }
            }
            if (lane == 0) { outv[k] = mv; outi[k] = mi; }
            if (bi == mi) cv[br] = -INFINITY;   // unique index -> one owner
        }
    }
    __syncthreads();

    if (tid < OUT_LEN) {
        float v = outv[tid];
        int   i = outi[tid];
        float o = 0.0f;                               // pad-with-zero path
        if (isfinite(v)) o = (float)spred[i];
        out[(size_t)b * OUT_LEN + tid] = o;
    }
}

// ---------------------------------------------------------------------------
extern "C" void kernel_launch(void* const* d_in, const int* in_sizes, int n_in,
                              void* d_out, int out_size) {
    const float* x = (const float*)d_in[0];
    float* out = (float*)d_out;

    fused_kernel<<<B_SAMPLES, THREADS>>>(x, out);
}

// round 7
// speedup vs baseline: 1.3666x; 1.0052x over previous
#include <cuda_runtime.h>
#include <math.h>

#define B_SAMPLES 128
#define T_LEN     8192
#define C_CLASSES 64
#define OUT_LEN   8

#define THREADS   1024
#define POS_PER_PASS (THREADS / 4)        // 4 threads per position -> 256
#define N_PASSES  (T_LEN / POS_PER_PASS)  // 32
#define EPT       (T_LEN / THREADS)       // 8 contiguous elems per thread

// ---------------------------------------------------------------------------
// Fused kernel: one CTA per sample.
// Phase 1 (stream): softmax confidence + argmax, 4 threads/position,
//   coalesced float4 loads; fast-math exp (MUFU.EX2) — issue-load trimmed.
// Phase 2 (tail): RLE + top-8 by voted confidence, all smem/registers.
// ---------------------------------------------------------------------------
__global__ __launch_bounds__(THREADS, 1)
void fused_kernel(const float* __restrict__ x, float* __restrict__ out) {
    __shared__ float         sconf[T_LEN];          // 32 KB
    __shared__ unsigned char spred[T_LEN];          //  8 KB
    __shared__ float candv[OUT_LEN * 32];           // [round][warp]
    __shared__ int   candi[OUT_LEN * 32];
    __shared__ float outv[OUT_LEN];
    __shared__ int   outi[OUT_LEN];

    const int b    = blockIdx.x;
    const int tid  = threadIdx.x;
    const int lane = tid & 31;
    const int wid  = tid >> 5;
    const int part = tid & 3;                       // 16-class chunk
    const int posL = tid >> 2;                      // position within pass

    const float* __restrict__ xb = x + (size_t)b * T_LEN * C_CLASSES;

    // ================= Phase 1: stream 2MB, compute conf/pred =================
    for (int pass = 0; pass < N_PASSES; pass++) {
        const int pos = pass * POS_PER_PASS + posL;
        const float4* __restrict__ p =
            (const float4*)(xb + (size_t)pos * C_CLASSES + part * 16);
        float4 v0 = p[0], v1 = p[1], v2 = p[2], v3 = p[3];

        float r[16] = {v0.x, v0.y, v0.z, v0.w, v1.x, v1.y, v1.z, v1.w,
                       v2.x, v2.y, v2.z, v2.w, v3.x, v3.y, v3.z, v3.w};

        // Value max via FMNMX chain (no index bookkeeping in the hot scan)
        float m = r[0];
        #pragma unroll
        for (int c = 1; c < 16; c++) m = fmaxf(m, r[c]);

        // First-occurrence argmax: descending >= (r[c] <= m, so >= means ==)
        int am = 0;
        #pragma unroll
        for (int c = 15; c >= 0; c--)
            if (r[c] >= m) am = c;
        int amg = part * 16 + am;

        // Combine across the 4 cooperating lanes (xor 1,2 stays in group)
        #pragma unroll
        for (int d = 1; d < 4; d <<= 1) {
            float om = __shfl_xor_sync(0xFFFFFFFFu, m,   d);
            int   oa = __shfl_xor_sync(0xFFFFFFFFu, amg, d);
            if (om > m || (om == m && oa < amg)) { m = om; amg = oa; }
        }

        // Fast exp: FMUL + MUFU.EX2 (rel err ~2^-22, within selection margin)
        float s = 0.0f;
        #pragma unroll
        for (int c = 0; c < 16; c++)
            s += __expf(r[c] - m);
        #pragma unroll
        for (int d = 1; d < 4; d <<= 1)
            s += __shfl_xor_sync(0xFFFFFFFFu, s, d);

        if (part == 0) {
            sconf[pos] = __fdividef(1.0f, s);
            spred[pos] = (unsigned char)amg;
        }
    }
    __syncthreads();

    // ================= Phase 2: RLE + top-8 (smem/registers) =================
    const int t0 = tid * EPT;

    uint2 pv2 = ((const uint2*)spred)[tid];
    unsigned char pb[EPT];
    pb[0] = (unsigned char)(pv2.x);        pb[1] = (unsigned char)(pv2.x >> 8);
    pb[2] = (unsigned char)(pv2.x >> 16);  pb[3] = (unsigned char)(pv2.x >> 24);
    pb[4] = (unsigned char)(pv2.y);        pb[5] = (unsigned char)(pv2.y >> 8);
    pb[6] = (unsigned char)(pv2.y >> 16);  pb[7] = (unsigned char)(pv2.y >> 24);

    float4 c0 = ((const float4*)sconf)[tid * 2];
    float4 c1 = ((const float4*)sconf)[tid * 2 + 1];
    float cf[EPT] = {c0.x, c0.y, c0.z, c0.w, c1.x, c1.y, c1.z, c1.w};

    unsigned char prev = (tid == 0) ? (unsigned char)(pb[0] ^ 1) : spred[t0 - 1];

    float lv[EPT];
    #pragma unroll
    for (int j = 0; j < EPT; j++) {
        unsigned char cur = pb[j];
        unsigned char before = (j == 0) ? prev : pb[j - 1];
        bool start = (t0 + j == 0) || (cur != before);
        float v = -INFINITY;
        if (start) {
            int cnt = 1;
            int jj = j + 1;
            while (jj < EPT && pb[jj] == cur) { cnt++; jj++; }   // reg scan
            if (jj == EPT) {                                      // rare spill
                int e = t0 + EPT;
                while (e < T_LEN && spred[e] == cur) { cnt++; e++; }
            }
            v = cf[j] * (float)cnt;
        }
        lv[j] = v;
    }

    // ---- Phase A: per-warp top-8 (no barriers) ----
    #pragma unroll
    for (int k = 0; k < OUT_LEN; k++) {
        float bv = lv[0];
        int   bj = 0;
        #pragma unroll
        for (int j = 1; j < EPT; j++)
            if (lv[j] > bv) { bv = lv[j]; bj = j; }   // j asc = index asc
        int bi = t0 + bj;

        #pragma unroll
        for (int d = 16; d > 0; d >>= 1) {
            float ov = __shfl_xor_sync(0xFFFFFFFFu, bv, d);
            int   oi = __shfl_xor_sync(0xFFFFFFFFu, bi, d);
            if (ov > bv || (ov == bv && oi < bi)) { bv = ov; bi = oi; }
        }
        if (lane == 0) {
            candv[k * 32 + wid] = bv;
            candi[k * 32 + wid] = bi;
        }
        if ((bi >> 3) == tid)              // owner invalidates
            lv[bi & (EPT - 1)] = -INFINITY;
    }
    __syncthreads();

    // ---- Phase B: warp 0 merges 32x8 candidates ----
    if (wid == 0) {
        float cv[OUT_LEN];
        int   ci[OUT_LEN];
        #pragma unroll
        for (int r = 0; r < OUT_LEN; r++) {
            cv[r] = candv[r * 32 + lane];
            ci[r] = candi[r * 32 + lane];
        }
        #pragma unroll
        for (int k = 0; k < OUT_LEN; k++) {
            // Per-lane candidates are value-desc / index-asc on ties, so a
            // strict > scan keeps the lowest-index tie, matching lax.top_k.
            float bv = cv[0];
            int   bi = ci[0], br = 0;
            #pragma unroll
            for (int r = 1; r < OUT_LEN; r++)
                if (cv[r] > bv) { bv = cv[r]; bi = ci[r]; br = r; }
            float mv = bv; int mi = bi;
            #pragma unroll
            for (int d = 16; d > 0; d >>= 1) {
                float ov = __shfl_xor_sync(0xFFFFFFFFu, mv, d);
                int   oi = __shfl_xor_sync(0xFFFFFFFFu, mi, d);
                if (ov > mv || (ov == mv && oi < mi)) { mv = ov; mi = oi; }
            }
            if (lane == 0) { outv[k] = mv; outi[k] = mi; }
            if (bi == mi) cv[br] = -INFINITY;   // unique index -> one owner
        }
    }
    __syncthreads();

    if (tid < OUT_LEN) {
        float v = outv[tid];
        int   i = outi[tid];
        float o = 0.0f;                               // pad-with-zero path
        if (isfinite(v)) o = (float)spred[i];
        out[(size_t)b * OUT_LEN + tid] = o;
    }
}

// ---------------------------------------------------------------------------
extern "C" void kernel_launch(void* const* d_in, const int* in_sizes, int n_in,
                              void* d_out, int out_size) {
    const float* x = (const float*)d_in[0];
    float* out = (float*)d_out;

    fused_kernel<<<B_SAMPLES, THREADS>>>(x, out);
}